// round 12
// baseline (speedup 1.0000x reference)
#include <cuda_runtime.h>
#include <cuda_bf16.h>
#include <math.h>
#include <float.h>
#include <stdint.h>

#define BATCH 2
#define NCTX  2048
#define DIM   512
#define HEADS 8
#define DHEAD 64
#define KNN   32
#define MDB   131072
#define MROWS (BATCH*NCTX)   // 4096
#define KS    1024           // bf16 storage: [hi(512) | lo(512)]
#define NCH   24             // logical K' = 1536 = 24 chunks of 64

// scratch (device globals; no allocation allowed)
__device__ float g_q[MROWS * DIM];
__device__ __nv_bfloat16 g_a2[(size_t)MROWS * KS];   // 8 MB
__device__ __nv_bfloat16 g_b2q[(size_t)DIM * KS];    // 1 MB
__device__ __nv_bfloat16 g_b2o[(size_t)DIM * KS];    // 1 MB

__device__ __forceinline__ uint32_t smem_u32(const void* p) {
    uint32_t a;
    asm("{ .reg .u64 t; cvta.to.shared.u64 t, %1; cvt.u32.u64 %0, t; }" : "=r"(a) : "l"(p));
    return a;
}
#define SW128(x) ((x) ^ (((x) >> 3) & 0x70))

#define LDSM_X4(r0, r1, r2, r3, addr) \
    asm volatile("ldmatrix.sync.aligned.m8n8.x4.shared.b16 {%0,%1,%2,%3}, [%4];" \
        : "=r"(r0), "=r"(r1), "=r"(r2), "=r"(r3) : "r"(addr))

#define MMA16816(c, a, b0, b1) \
    asm volatile("mma.sync.aligned.m16n8k16.row.col.f32.bf16.bf16.f32 " \
        "{%0,%1,%2,%3}, {%4,%5,%6,%7}, {%8,%9}, {%0,%1,%2,%3};" \
        : "+f"((c)[0]), "+f"((c)[1]), "+f"((c)[2]), "+f"((c)[3]) \
        : "r"((a)[0]), "r"((a)[1]), "r"((a)[2]), "r"((a)[3]), "r"(b0), "r"(b1))

#define CP_ASYNC16(dst, src) \
    asm volatile("cp.async.cg.shared.global [%0], [%1], 16;" :: "r"(dst), "l"(src))
#define CP_COMMIT() asm volatile("cp.async.commit_group;" ::: "memory")
#define CP_WAIT1()  asm volatile("cp.async.wait_group 1;" ::: "memory")

// ---------------------------------------------------------------------------
// split helper: 4 fp32 -> packed bf16 hi (ull) and lo (ull)
// ---------------------------------------------------------------------------
__device__ __forceinline__ void split_pack4(const float* vv,
                                            unsigned long long& hp,
                                            unsigned long long& lp)
{
    hp = 0; lp = 0;
#pragma unroll
    for (int i = 0; i < 4; i++) {
        __nv_bfloat16 h = __float2bfloat16(vv[i]);
        __nv_bfloat16 l = __float2bfloat16(vv[i] - __bfloat162float(h));
        hp |= (unsigned long long)__bfloat16_as_ushort(h) << (16 * i);
        lp |= (unsigned long long)__bfloat16_as_ushort(l) << (16 * i);
    }
}

__device__ __forceinline__ void split_row4(const float* __restrict__ src,
                                           __nv_bfloat16* __restrict__ dst)
{
    float4 v = *(const float4*)src;
    float vv[4] = {v.x, v.y, v.z, v.w};
    unsigned long long hp, lp;
    split_pack4(vv, hp, lp);
    *(unsigned long long*)(dst)       = hp;
    *(unsigned long long*)(dst + 512) = lp;
}

// split all inputs in one launch: x (4096 rows), Wq (512), Wout (512)
__global__ void split_all(const float* __restrict__ x,
                          const float* __restrict__ Wq,
                          const float* __restrict__ Wout)
{
    int idx = blockIdx.x * blockDim.x + threadIdx.x;   // over 5120*(512/4)
    int r  = idx / (DIM / 4);
    int c4 = (idx % (DIM / 4)) * 4;
    if (r < MROWS) {
        split_row4(x + (long)r * DIM + c4, g_a2 + (long)r * KS + c4);
    } else if (r < MROWS + DIM) {
        int rr = r - MROWS;
        split_row4(Wq + (long)rr * DIM + c4, g_b2q + (long)rr * KS + c4);
    } else {
        int rr = r - MROWS - DIM;
        split_row4(Wout + (long)rr * DIM + c4, g_b2o + (long)rr * KS + c4);
    }
}

// ---------------------------------------------------------------------------
// bf16 mma.sync GEMM, cp.async 3-stage pipeline, 2 CTAs/SM.
// C = A*B^T, emulated-fp32 3-term schedule (K'=1536 over [hi|lo] storage).
// CTA tile 128x64 (M x N), 8 warps (2x4), warp tile 64x16, BK=64.
// grid = (N/64, M/128) = (8, 32) = 256 CTAs.
// ---------------------------------------------------------------------------
#define SA_TILE (128 * 128)       // 16 KB
#define SB_TILE (64 * 128)        // 8 KB
#define SA_OFF(s) ((s) * SA_TILE)
#define SB_OFF(s) (3 * SA_TILE + (s) * SB_TILE)
#define GSMEM  (3 * SA_TILE + 3 * SB_TILE)   // 72 KB

__device__ __forceinline__ int a_src(int c) { return (c < 8) ? c : c - 8; }
__device__ __forceinline__ int b_src(int c) { return (c < 16) ? c : c - 16; }

__global__ void __launch_bounds__(256, 2) gemm_mma(
    const __nv_bfloat16* __restrict__ A,
    const __nv_bfloat16* __restrict__ B,
    float* __restrict__ C, int N)
{
    extern __shared__ char smem[];
    uint32_t sb = smem_u32(smem);
    const int tid  = threadIdx.x;
    const int wid  = tid >> 5, lane = tid & 31;
    const int wr   = wid >> 2;          // 0..1 (m block of 64)
    const int wc   = wid & 3;           // 0..3 (n block of 16)
    const int row0 = blockIdx.y * 128, col0 = blockIdx.x * 64;

    // A staging: 128 rows x 64 cols bf16 (128B rows): 1024 x 16B, 4/thread
    const int sr = tid >> 3;            // 0..31
    const int sc = (tid & 7) * 16;      // byte col
    // B staging: 64 rows x 128B = 512 x 16B, 2/thread
    const int br = tid >> 3;            // 0..31 (use rows br, br+32)

    const uint32_t a_l = (uint32_t)((lane & 15) * 128 + ((lane >> 4) & 1) * 16);
    const uint32_t b_l = (uint32_t)(((lane & 7) + ((lane >> 4) & 1) * 8) * 128 + ((lane >> 3) & 1) * 16);

    float acc[4][2][4];
#pragma unroll
    for (int i = 0; i < 4; i++)
#pragma unroll
        for (int j = 0; j < 2; j++)
#pragma unroll
            for (int k = 0; k < 4; k++) acc[i][j][k] = 0.f;

    // issue chunk cc's copies into stage s, one commit group
#define ISSUE(cc, s) do { \
        int ka = a_src(cc) * 64, kb = b_src(cc) * 64; \
        _Pragma("unroll") \
        for (int i = 0; i < 4; i++) { \
            int r = sr + i * 32; \
            uint32_t da = sb + SA_OFF(s) + SW128(r * 128 + sc); \
            CP_ASYNC16(da, A + (long)(row0 + r) * KS + ka + (sc >> 1)); \
        } \
        _Pragma("unroll") \
        for (int i = 0; i < 2; i++) { \
            int r = br + i * 32; \
            uint32_t dbm = sb + SB_OFF(s) + SW128(r * 128 + sc); \
            CP_ASYNC16(dbm, B + (long)(col0 + r) * KS + kb + (sc >> 1)); \
        } \
        CP_COMMIT(); \
    } while (0)

    ISSUE(0, 0);
    ISSUE(1, 1);

    for (int c = 0; c < NCH; c++) {
        int s = c % 3;
        CP_WAIT1();
        __syncthreads();

        uint32_t sa  = sb + SA_OFF(s) + wr * (64 * 128);
        uint32_t sbm = sb + SB_OFF(s) + wc * (16 * 128);

#pragma unroll
        for (int ks = 0; ks < 4; ks++) {
            // B: 16 cols = 2 n8-tiles -> one LDSM_X4
            uint32_t bf[4];
            LDSM_X4(bf[0], bf[1], bf[2], bf[3], sbm + SW128(b_l + ks * 32));
#pragma unroll
            for (int mt = 0; mt < 4; mt++) {
                uint32_t af[4];
                uint32_t x = a_l + mt * 2048 + ks * 32;
                LDSM_X4(af[0], af[1], af[2], af[3], sa + SW128(x));
#pragma unroll
                for (int nt = 0; nt < 2; nt++)
                    MMA16816(acc[mt][nt], af, bf[nt * 2], bf[nt * 2 + 1]);
            }
        }
        __syncthreads();

        if (c + 2 < NCH) ISSUE(c + 2, (c + 2) % 3);
    }

    const int qr = lane >> 2, qc = (lane & 3) * 2;
#pragma unroll
    for (int mt = 0; mt < 4; mt++) {
#pragma unroll
        for (int nt = 0; nt < 2; nt++) {
            int r = row0 + wr * 64 + mt * 16 + qr;
            int cc = col0 + wc * 16 + nt * 8 + qc;
            *(float2*)(C + (long)r * N + cc)       = make_float2(acc[mt][nt][0], acc[mt][nt][1]);
            *(float2*)(C + (long)(r + 8) * N + cc) = make_float2(acc[mt][nt][2], acc[mt][nt][3]);
        }
    }
#undef ISSUE
}

// ---------------------------------------------------------------------------
// KNN attention v5: paired-neighbor low-shuffle core + fused bf16 epilogue.
// ---------------------------------------------------------------------------
__global__ void __launch_bounds__(256) knn_attn5(
    const float* __restrict__ mem_db,
    const int*   __restrict__ knn_idx,
    const int*   __restrict__ mem_mask,
    const float* __restrict__ scale_param)
{
    __shared__ int   s_idx[8][32];
    __shared__ float s_q[8][64];
    __shared__ float s_sim[8][32];
    __shared__ float s_att[8][32];
    const unsigned FULL = 0xffffffffu;
    const int tid = threadIdx.x, lane = tid & 31, w = tid >> 5;

    const int warp = blockIdx.x * 8 + w;          // 0..32767
    const int n  = warp & (NCTX - 1);
    const int bh = warp >> 11;
    const int h  = bh & (HEADS - 1);
    const int b  = bh >> 3;

    const float* qp = g_q + ((long)(b * NCTX + n) * DIM) + h * DHEAD;
    float q0 = qp[lane], q1 = qp[lane + 32];
    float ssum = q0 * q0 + q1 * q1;
#pragma unroll
    for (int o = 16; o > 0; o >>= 1) ssum += __shfl_xor_sync(FULL, ssum, o);
    float inv = expf(scale_param[h]) / fmaxf(sqrtf(ssum), 1e-12f);
    s_q[w][lane]      = q0 * inv;
    s_q[w][lane + 32] = q1 * inv;

    long ib = (long)((b * HEADS + h) * NCTX + n) * KNN;
    s_idx[w][lane] = knn_idx[ib + lane];
    int msk = mem_mask[ib + lane];
    __syncwarp();

    const float* db = mem_db + (long)b * MDB * 128;
    const int hl = lane >> 4;
    const int sl = lane & 15;

    float4 q4 = *(const float4*)&s_q[w][sl * 4];

#pragma unroll 4
    for (int i = 0; i < 16; i++) {
        int  nb = 2 * i + hl;
        long ij = s_idx[w][nb];
        float4 k4 = *(const float4*)(db + ij * 128 + sl * 4);
        float p = fmaf(q4.x, k4.x, fmaf(q4.y, k4.y, fmaf(q4.z, k4.z, q4.w * k4.w)));
        p += __shfl_xor_sync(FULL, p, 8);
        p += __shfl_xor_sync(FULL, p, 4);
        p += __shfl_xor_sync(FULL, p, 2);
        p += __shfl_xor_sync(FULL, p, 1);
        if (sl == 0) s_sim[w][nb] = p;
    }
    __syncwarp();

    float sim = msk ? s_sim[w][lane] : -FLT_MAX;

    float m = sim;
#pragma unroll
    for (int o = 16; o > 0; o >>= 1) m = fmaxf(m, __shfl_xor_sync(FULL, m, o));
    float p = __expf(sim - m);
    float s = p;
#pragma unroll
    for (int o = 16; o > 0; o >>= 1) s += __shfl_xor_sync(FULL, s, o);
    s_att[w][lane] = p / s;
    __syncwarp();

    float4 acc = make_float4(0.f, 0.f, 0.f, 0.f);
#pragma unroll 4
    for (int i = 0; i < 16; i++) {
        int  nb = 2 * i + hl;
        long ij = s_idx[w][nb];
        float a = s_att[w][nb];
        float4 v4 = *(const float4*)(db + ij * 128 + 64 + sl * 4);
        acc.x = fmaf(a, v4.x, acc.x);
        acc.y = fmaf(a, v4.y, acc.y);
        acc.z = fmaf(a, v4.z, acc.z);
        acc.w = fmaf(a, v4.w, acc.w);
    }
    acc.x += __shfl_xor_sync(FULL, acc.x, 16);
    acc.y += __shfl_xor_sync(FULL, acc.y, 16);
    acc.z += __shfl_xor_sync(FULL, acc.z, 16);
    acc.w += __shfl_xor_sync(FULL, acc.w, 16);

    if (lane < 16) {
        float vv[4] = {acc.x, acc.y, acc.z, acc.w};
        unsigned long long hp, lp;
        split_pack4(vv, hp, lp);
        __nv_bfloat16* dst = g_a2 + (long)(b * NCTX + n) * KS + h * DHEAD + sl * 4;
        *(unsigned long long*)(dst)       = hp;
        *(unsigned long long*)(dst + 512) = lp;
    }
}

// ---------------------------------------------------------------------------
extern "C" void kernel_launch(void* const* d_in, const int* in_sizes, int n_in,
                              void* d_out, int out_size)
{
    const float* x        = (const float*)d_in[0];
    const float* mem_db   = (const float*)d_in[1];
    const int*   knn_idx  = (const int*)d_in[2];
    const int*   mem_mask = (const int*)d_in[3];
    const float* Wq       = (const float*)d_in[4];
    // d_in[5] = Wkv : dead code in the reference, never used
    const float* Wout     = (const float*)d_in[6];
    const float* scale_p  = (const float*)d_in[7];
    float* out = (float*)d_out;

    float *qb;
    __nv_bfloat16 *a2, *b2q, *b2o;
    cudaGetSymbolAddress((void**)&qb,  g_q);
    cudaGetSymbolAddress((void**)&a2,  g_a2);
    cudaGetSymbolAddress((void**)&b2q, g_b2q);
    cudaGetSymbolAddress((void**)&b2o, g_b2o);

    cudaFuncSetAttribute(gemm_mma, cudaFuncAttributeMaxDynamicSharedMemorySize, GSMEM);

    dim3 gGemm(DIM / 64, MROWS / 128);   // (8, 32) = 256 CTAs

    // 1) split x, Wq, Wout in one launch; then q = x @ Wq^T
    split_all<<<((MROWS + 2 * DIM) * (DIM / 4)) / 256, 256>>>(x, Wq, Wout);
    gemm_mma<<<gGemm, 256, GSMEM>>>(a2, b2q, qb, DIM);

    // 2) gather-attention; epilogue writes bf16 split directly into g_a2
    int nwarps = BATCH * HEADS * NCTX;            // 32768
    knn_attn5<<<nwarps / 8, 256>>>(mem_db, knn_idx, mem_mask, scale_p);

    // 3) out = attn_out @ Wout^T
    gemm_mma<<<gGemm, 256, GSMEM>>>(a2, b2o, out, DIM);
}

// round 13
// speedup vs baseline: 1.1439x; 1.1439x over previous
#include <cuda_runtime.h>
#include <cuda_fp16.h>
#include <math.h>
#include <float.h>
#include <stdint.h>

#define BATCH 2
#define NCTX  2048
#define DIM   512
#define HEADS 8
#define DHEAD 64
#define KNN   32
#define MDB   131072
#define MROWS (BATCH*NCTX)   // 4096
#define KS    1024           // fp16 A storage: [hi(512) | lo(512)]
#define KBW   512            // fp16 B storage: hi only
#define NCH   16             // logical K' = 1024 = 16 chunks of 64

// scratch (device globals; no allocation allowed)
__device__ float g_q[MROWS * DIM];
__device__ __half g_a2[(size_t)MROWS * KS];   // 8 MB
__device__ __half g_b2q[(size_t)DIM * KBW];   // 0.5 MB
__device__ __half g_b2o[(size_t)DIM * KBW];   // 0.5 MB

__device__ __forceinline__ uint32_t smem_u32(const void* p) {
    uint32_t a;
    asm("{ .reg .u64 t; cvta.to.shared.u64 t, %1; cvt.u32.u64 %0, t; }" : "=r"(a) : "l"(p));
    return a;
}
#define SW128(x) ((x) ^ (((x) >> 3) & 0x70))

#define LDSM_X4(r0, r1, r2, r3, addr) \
    asm volatile("ldmatrix.sync.aligned.m8n8.x4.shared.b16 {%0,%1,%2,%3}, [%4];" \
        : "=r"(r0), "=r"(r1), "=r"(r2), "=r"(r3) : "r"(addr))

#define MMA16816(c, a, b0, b1) \
    asm volatile("mma.sync.aligned.m16n8k16.row.col.f32.f16.f16.f32 " \
        "{%0,%1,%2,%3}, {%4,%5,%6,%7}, {%8,%9}, {%0,%1,%2,%3};" \
        : "+f"((c)[0]), "+f"((c)[1]), "+f"((c)[2]), "+f"((c)[3]) \
        : "r"((a)[0]), "r"((a)[1]), "r"((a)[2]), "r"((a)[3]), "r"(b0), "r"(b1))

#define CP_ASYNC16(dst, src) \
    asm volatile("cp.async.cg.shared.global [%0], [%1], 16;" :: "r"(dst), "l"(src))
#define CP_COMMIT() asm volatile("cp.async.commit_group;" ::: "memory")
#define CP_WAIT1()  asm volatile("cp.async.wait_group 1;" ::: "memory")

// ---------------------------------------------------------------------------
// split helper: 4 fp32 -> packed fp16 hi (ull) and lo (ull)
// ---------------------------------------------------------------------------
__device__ __forceinline__ void split_pack4(const float* vv,
                                            unsigned long long& hp,
                                            unsigned long long& lp)
{
    hp = 0; lp = 0;
#pragma unroll
    for (int i = 0; i < 4; i++) {
        __half h = __float2half(vv[i]);
        __half l = __float2half(vv[i] - __half2float(h));
        hp |= (unsigned long long)__half_as_ushort(h) << (16 * i);
        lp |= (unsigned long long)__half_as_ushort(l) << (16 * i);
    }
}

// A rows: [hi | lo]
__device__ __forceinline__ void split_row4_a(const float* __restrict__ src,
                                             __half* __restrict__ dst)
{
    float4 v = *(const float4*)src;
    float vv[4] = {v.x, v.y, v.z, v.w};
    unsigned long long hp, lp;
    split_pack4(vv, hp, lp);
    *(unsigned long long*)(dst)       = hp;
    *(unsigned long long*)(dst + 512) = lp;
}

// B rows: hi only
__device__ __forceinline__ void cvt_row4_b(const float* __restrict__ src,
                                           __half* __restrict__ dst)
{
    float4 v = *(const float4*)src;
    float vv[4] = {v.x, v.y, v.z, v.w};
    unsigned long long hp = 0;
#pragma unroll
    for (int i = 0; i < 4; i++)
        hp |= (unsigned long long)__half_as_ushort(__float2half(vv[i])) << (16 * i);
    *(unsigned long long*)(dst) = hp;
}

// split all inputs in one launch: x (4096 rows, hi/lo), Wq (512), Wout (512)
__global__ void split_all(const float* __restrict__ x,
                          const float* __restrict__ Wq,
                          const float* __restrict__ Wout)
{
    int idx = blockIdx.x * blockDim.x + threadIdx.x;   // over 5120*(512/4)
    int r  = idx / (DIM / 4);
    int c4 = (idx % (DIM / 4)) * 4;
    if (r < MROWS) {
        split_row4_a(x + (long)r * DIM + c4, g_a2 + (long)r * KS + c4);
    } else if (r < MROWS + DIM) {
        int rr = r - MROWS;
        cvt_row4_b(Wq + (long)rr * DIM + c4, g_b2q + (long)rr * KBW + c4);
    } else {
        int rr = r - MROWS - DIM;
        cvt_row4_b(Wout + (long)rr * DIM + c4, g_b2o + (long)rr * KBW + c4);
    }
}

// ---------------------------------------------------------------------------
// fp16 mma.sync GEMM, cp.async 3-stage pipeline.
// C = A*B^T, 2-term emulated-fp32: K'=1024; chunk c<8 -> A-hi, c>=8 -> A-lo;
// B always hi block (c&7).
// CTA tile 128x64 (M x N), 8 warps (2x4), warp tile 64x16, BK=64.
// grid = (N/64, M/128) = (8, 32) = 256 CTAs.
// ---------------------------------------------------------------------------
#define SA_TILE (128 * 128)       // 16 KB
#define SB_TILE (64 * 128)        // 8 KB
#define SA_OFF(s) ((s) * SA_TILE)
#define SB_OFF(s) (3 * SA_TILE + (s) * SB_TILE)
#define GSMEM  (3 * SA_TILE + 3 * SB_TILE)   // 72 KB

__global__ void __launch_bounds__(256, 2) gemm_mma(
    const __half* __restrict__ A,
    const __half* __restrict__ B,
    float* __restrict__ C, int N)
{
    extern __shared__ char smem[];
    uint32_t sb = smem_u32(smem);
    const int tid  = threadIdx.x;
    const int wid  = tid >> 5, lane = tid & 31;
    const int wr   = wid >> 2;          // 0..1 (m block of 64)
    const int wc   = wid & 3;           // 0..3 (n block of 16)
    const int row0 = blockIdx.y * 128, col0 = blockIdx.x * 64;

    const int sr = tid >> 3;            // 0..31
    const int sc = (tid & 7) * 16;      // byte col
    const int br = tid >> 3;

    const uint32_t a_l = (uint32_t)((lane & 15) * 128 + ((lane >> 4) & 1) * 16);
    const uint32_t b_l = (uint32_t)(((lane & 7) + ((lane >> 4) & 1) * 8) * 128 + ((lane >> 3) & 1) * 16);

    float acc[4][2][4];
#pragma unroll
    for (int i = 0; i < 4; i++)
#pragma unroll
        for (int j = 0; j < 2; j++)
#pragma unroll
            for (int k = 0; k < 4; k++) acc[i][j][k] = 0.f;

#define ISSUE(cc, s) do { \
        int ka = ((cc) < 8) ? (cc) * 64 : 512 + ((cc) - 8) * 64; \
        int kb = ((cc) & 7) * 64; \
        _Pragma("unroll") \
        for (int i = 0; i < 4; i++) { \
            int r = sr + i * 32; \
            uint32_t da = sb + SA_OFF(s) + SW128(r * 128 + sc); \
            CP_ASYNC16(da, A + (long)(row0 + r) * KS + ka + (sc >> 1)); \
        } \
        _Pragma("unroll") \
        for (int i = 0; i < 2; i++) { \
            int r = br + i * 32; \
            uint32_t dbm = sb + SB_OFF(s) + SW128(r * 128 + sc); \
            CP_ASYNC16(dbm, B + (long)(col0 + r) * KBW + kb + (sc >> 1)); \
        } \
        CP_COMMIT(); \
    } while (0)

    ISSUE(0, 0);
    ISSUE(1, 1);

    for (int c = 0; c < NCH; c++) {
        int s = c % 3;
        CP_WAIT1();
        __syncthreads();

        uint32_t sa  = sb + SA_OFF(s) + wr * (64 * 128);
        uint32_t sbm = sb + SB_OFF(s) + wc * (16 * 128);

#pragma unroll
        for (int ks = 0; ks < 4; ks++) {
            uint32_t bf[4];
            LDSM_X4(bf[0], bf[1], bf[2], bf[3], sbm + SW128(b_l + ks * 32));
#pragma unroll
            for (int mt = 0; mt < 4; mt++) {
                uint32_t af[4];
                uint32_t x = a_l + mt * 2048 + ks * 32;
                LDSM_X4(af[0], af[1], af[2], af[3], sa + SW128(x));
#pragma unroll
                for (int nt = 0; nt < 2; nt++)
                    MMA16816(acc[mt][nt], af, bf[nt * 2], bf[nt * 2 + 1]);
            }
        }
        __syncthreads();

        if (c + 2 < NCH) ISSUE(c + 2, (c + 2) % 3);
    }

    const int qr = lane >> 2, qc = (lane & 3) * 2;
#pragma unroll
    for (int mt = 0; mt < 4; mt++) {
#pragma unroll
        for (int nt = 0; nt < 2; nt++) {
            int r = row0 + wr * 64 + mt * 16 + qr;
            int cc = col0 + wc * 16 + nt * 8 + qc;
            *(float2*)(C + (long)r * N + cc)       = make_float2(acc[mt][nt][0], acc[mt][nt][1]);
            *(float2*)(C + (long)(r + 8) * N + cc) = make_float2(acc[mt][nt][2], acc[mt][nt][3]);
        }
    }
#undef ISSUE
}

// ---------------------------------------------------------------------------
// KNN attention v5: paired-neighbor low-shuffle core + fused fp16 epilogue.
// ---------------------------------------------------------------------------
__global__ void __launch_bounds__(256) knn_attn5(
    const float* __restrict__ mem_db,
    const int*   __restrict__ knn_idx,
    const int*   __restrict__ mem_mask,
    const float* __restrict__ scale_param)
{
    __shared__ int   s_idx[8][32];
    __shared__ float s_q[8][64];
    __shared__ float s_sim[8][32];
    __shared__ float s_att[8][32];
    const unsigned FULL = 0xffffffffu;
    const int tid = threadIdx.x, lane = tid & 31, w = tid >> 5;

    const int warp = blockIdx.x * 8 + w;          // 0..32767
    const int n  = warp & (NCTX - 1);
    const int bh = warp >> 11;
    const int h  = bh & (HEADS - 1);
    const int b  = bh >> 3;

    const float* qp = g_q + ((long)(b * NCTX + n) * DIM) + h * DHEAD;
    float q0 = qp[lane], q1 = qp[lane + 32];
    float ssum = q0 * q0 + q1 * q1;
#pragma unroll
    for (int o = 16; o > 0; o >>= 1) ssum += __shfl_xor_sync(FULL, ssum, o);
    float inv = expf(scale_param[h]) / fmaxf(sqrtf(ssum), 1e-12f);
    s_q[w][lane]      = q0 * inv;
    s_q[w][lane + 32] = q1 * inv;

    long ib = (long)((b * HEADS + h) * NCTX + n) * KNN;
    s_idx[w][lane] = knn_idx[ib + lane];
    int msk = mem_mask[ib + lane];
    __syncwarp();

    const float* db = mem_db + (long)b * MDB * 128;
    const int hl = lane >> 4;
    const int sl = lane & 15;

    float4 q4 = *(const float4*)&s_q[w][sl * 4];

#pragma unroll 4
    for (int i = 0; i < 16; i++) {
        int  nb = 2 * i + hl;
        long ij = s_idx[w][nb];
        float4 k4 = *(const float4*)(db + ij * 128 + sl * 4);
        float p = fmaf(q4.x, k4.x, fmaf(q4.y, k4.y, fmaf(q4.z, k4.z, q4.w * k4.w)));
        p += __shfl_xor_sync(FULL, p, 8);
        p += __shfl_xor_sync(FULL, p, 4);
        p += __shfl_xor_sync(FULL, p, 2);
        p += __shfl_xor_sync(FULL, p, 1);
        if (sl == 0) s_sim[w][nb] = p;
    }
    __syncwarp();

    float sim = msk ? s_sim[w][lane] : -FLT_MAX;

    float m = sim;
#pragma unroll
    for (int o = 16; o > 0; o >>= 1) m = fmaxf(m, __shfl_xor_sync(FULL, m, o));
    float p = __expf(sim - m);
    float s = p;
#pragma unroll
    for (int o = 16; o > 0; o >>= 1) s += __shfl_xor_sync(FULL, s, o);
    s_att[w][lane] = p / s;
    __syncwarp();

    float4 acc = make_float4(0.f, 0.f, 0.f, 0.f);
#pragma unroll 4
    for (int i = 0; i < 16; i++) {
        int  nb = 2 * i + hl;
        long ij = s_idx[w][nb];
        float a = s_att[w][nb];
        float4 v4 = *(const float4*)(db + ij * 128 + 64 + sl * 4);
        acc.x = fmaf(a, v4.x, acc.x);
        acc.y = fmaf(a, v4.y, acc.y);
        acc.z = fmaf(a, v4.z, acc.z);
        acc.w = fmaf(a, v4.w, acc.w);
    }
    acc.x += __shfl_xor_sync(FULL, acc.x, 16);
    acc.y += __shfl_xor_sync(FULL, acc.y, 16);
    acc.z += __shfl_xor_sync(FULL, acc.z, 16);
    acc.w += __shfl_xor_sync(FULL, acc.w, 16);

    if (lane < 16) {
        float vv[4] = {acc.x, acc.y, acc.z, acc.w};
        unsigned long long hp, lp;
        split_pack4(vv, hp, lp);
        __half* dst = g_a2 + (long)(b * NCTX + n) * KS + h * DHEAD + sl * 4;
        *(unsigned long long*)(dst)       = hp;
        *(unsigned long long*)(dst + 512) = lp;
    }
}

// ---------------------------------------------------------------------------
extern "C" void kernel_launch(void* const* d_in, const int* in_sizes, int n_in,
                              void* d_out, int out_size)
{
    const float* x        = (const float*)d_in[0];
    const float* mem_db   = (const float*)d_in[1];
    const int*   knn_idx  = (const int*)d_in[2];
    const int*   mem_mask = (const int*)d_in[3];
    const float* Wq       = (const float*)d_in[4];
    // d_in[5] = Wkv : dead code in the reference, never used
    const float* Wout     = (const float*)d_in[6];
    const float* scale_p  = (const float*)d_in[7];
    float* out = (float*)d_out;

    float *qb;
    __half *a2, *b2q, *b2o;
    cudaGetSymbolAddress((void**)&qb,  g_q);
    cudaGetSymbolAddress((void**)&a2,  g_a2);
    cudaGetSymbolAddress((void**)&b2q, g_b2q);
    cudaGetSymbolAddress((void**)&b2o, g_b2o);

    cudaFuncSetAttribute(gemm_mma, cudaFuncAttributeMaxDynamicSharedMemorySize, GSMEM);

    dim3 gGemm(DIM / 64, MROWS / 128);   // (8, 32) = 256 CTAs

    // 1) split x (hi/lo), Wq, Wout (hi); then q = x @ Wq^T
    split_all<<<((MROWS + 2 * DIM) * (DIM / 4)) / 256, 256>>>(x, Wq, Wout);
    gemm_mma<<<gGemm, 256, GSMEM>>>(a2, b2q, qb, DIM);

    // 2) gather-attention; epilogue writes fp16 split directly into g_a2
    int nwarps = BATCH * HEADS * NCTX;            // 32768
    knn_attn5<<<nwarps / 8, 256>>>(mem_db, knn_idx, mem_mask, scale_p);

    // 3) out = attn_out @ Wout^T
    gemm_mma<<<gGemm, 256, GSMEM>>>(a2, b2o, out, DIM);
}

// round 14
// speedup vs baseline: 1.1724x; 1.0249x over previous
#include <cuda_runtime.h>
#include <cuda_fp16.h>
#include <math.h>
#include <float.h>
#include <stdint.h>

#define BATCH 2
#define NCTX  2048
#define DIM   512
#define HEADS 8
#define DHEAD 64
#define KNN   32
#define MDB   131072
#define MROWS (BATCH*NCTX)   // 4096
#define KS    1024           // fp16 A storage: [hi(512) | lo(512)]
#define KBW   512            // fp16 B storage: hi only
#define NCH   16             // logical K' = 1024 = 16 chunks of 64

// scratch (device globals; no allocation allowed)
__device__ float g_q[MROWS * DIM];
__device__ __half g_a2[(size_t)MROWS * KS];   // 8 MB
__device__ __half g_b2q[(size_t)DIM * KBW];   // 0.5 MB
__device__ __half g_b2o[(size_t)DIM * KBW];   // 0.5 MB

__device__ __forceinline__ uint32_t smem_u32(const void* p) {
    uint32_t a;
    asm("{ .reg .u64 t; cvta.to.shared.u64 t, %1; cvt.u32.u64 %0, t; }" : "=r"(a) : "l"(p));
    return a;
}
#define SW128(x) ((x) ^ (((x) >> 3) & 0x70))

#define LDSM_X4(r0, r1, r2, r3, addr) \
    asm volatile("ldmatrix.sync.aligned.m8n8.x4.shared.b16 {%0,%1,%2,%3}, [%4];" \
        : "=r"(r0), "=r"(r1), "=r"(r2), "=r"(r3) : "r"(addr))

#define MMA16816(c, a, b0, b1) \
    asm volatile("mma.sync.aligned.m16n8k16.row.col.f32.f16.f16.f32 " \
        "{%0,%1,%2,%3}, {%4,%5,%6,%7}, {%8,%9}, {%0,%1,%2,%3};" \
        : "+f"((c)[0]), "+f"((c)[1]), "+f"((c)[2]), "+f"((c)[3]) \
        : "r"((a)[0]), "r"((a)[1]), "r"((a)[2]), "r"((a)[3]), "r"(b0), "r"(b1))

#define CP_ASYNC16(dst, src) \
    asm volatile("cp.async.cg.shared.global [%0], [%1], 16;" :: "r"(dst), "l"(src))
#define CP_COMMIT() asm volatile("cp.async.commit_group;" ::: "memory")
#define CP_WAIT1()  asm volatile("cp.async.wait_group 1;" ::: "memory")

// ---------------------------------------------------------------------------
// split helper: 4 fp32 -> packed fp16 hi (ull) and lo (ull)
// ---------------------------------------------------------------------------
__device__ __forceinline__ void split_pack4(const float* vv,
                                            unsigned long long& hp,
                                            unsigned long long& lp)
{
    hp = 0; lp = 0;
#pragma unroll
    for (int i = 0; i < 4; i++) {
        __half h = __float2half(vv[i]);
        __half l = __float2half(vv[i] - __half2float(h));
        hp |= (unsigned long long)__half_as_ushort(h) << (16 * i);
        lp |= (unsigned long long)__half_as_ushort(l) << (16 * i);
    }
}

// A rows: [hi | lo]
__device__ __forceinline__ void split_row4_a(const float* __restrict__ src,
                                             __half* __restrict__ dst)
{
    float4 v = *(const float4*)src;
    float vv[4] = {v.x, v.y, v.z, v.w};
    unsigned long long hp, lp;
    split_pack4(vv, hp, lp);
    *(unsigned long long*)(dst)       = hp;
    *(unsigned long long*)(dst + 512) = lp;
}

// B rows: hi only
__device__ __forceinline__ void cvt_row4_b(const float* __restrict__ src,
                                           __half* __restrict__ dst)
{
    float4 v = *(const float4*)src;
    float vv[4] = {v.x, v.y, v.z, v.w};
    unsigned long long hp = 0;
#pragma unroll
    for (int i = 0; i < 4; i++)
        hp |= (unsigned long long)__half_as_ushort(__float2half(vv[i])) << (16 * i);
    *(unsigned long long*)(dst) = hp;
}

// split all inputs in one launch: x (4096 rows, hi/lo), Wq (512), Wout (512)
__global__ void split_all(const float* __restrict__ x,
                          const float* __restrict__ Wq,
                          const float* __restrict__ Wout)
{
    int idx = blockIdx.x * blockDim.x + threadIdx.x;   // over 5120*(512/4)
    int r  = idx / (DIM / 4);
    int c4 = (idx % (DIM / 4)) * 4;
    if (r < MROWS) {
        split_row4_a(x + (long)r * DIM + c4, g_a2 + (long)r * KS + c4);
    } else if (r < MROWS + DIM) {
        int rr = r - MROWS;
        cvt_row4_b(Wq + (long)rr * DIM + c4, g_b2q + (long)rr * KBW + c4);
    } else {
        int rr = r - MROWS - DIM;
        cvt_row4_b(Wout + (long)rr * DIM + c4, g_b2o + (long)rr * KBW + c4);
    }
}

// ---------------------------------------------------------------------------
// fp16 mma.sync GEMM, cp.async 3-stage pipeline, 1 barrier/chunk.
// C = A*B^T, 2-term emulated-fp32: K'=1024; chunk c<8 -> A-hi, c>=8 -> A-lo;
// B always hi block (c&7).
// CTA tile 128x64 (M x N), 8 warps (2x4), warp tile 64x16, BK=64.
// grid = (N/64, M/128) = (8, 32) = 256 CTAs, 2 CTAs/SM.
// ---------------------------------------------------------------------------
#define SA_TILE (128 * 128)       // 16 KB
#define SB_TILE (64 * 128)        // 8 KB
#define SA_OFF(s) ((s) * SA_TILE)
#define SB_OFF(s) (3 * SA_TILE + (s) * SB_TILE)
#define GSMEM  (3 * SA_TILE + 3 * SB_TILE)   // 72 KB

__global__ void __launch_bounds__(256, 2) gemm_mma(
    const __half* __restrict__ A,
    const __half* __restrict__ B,
    float* __restrict__ C, int N)
{
    extern __shared__ char smem[];
    uint32_t sb = smem_u32(smem);
    const int tid  = threadIdx.x;
    const int wid  = tid >> 5, lane = tid & 31;
    const int wr   = wid >> 2;          // 0..1 (m block of 64)
    const int wc   = wid & 3;           // 0..3 (n block of 16)
    const int row0 = blockIdx.y * 128, col0 = blockIdx.x * 64;

    const int sr = tid >> 3;            // 0..31
    const int sc = (tid & 7) * 16;      // byte col
    const int br = tid >> 3;

    const uint32_t a_l = (uint32_t)((lane & 15) * 128 + ((lane >> 4) & 1) * 16);
    const uint32_t b_l = (uint32_t)(((lane & 7) + ((lane >> 4) & 1) * 8) * 128 + ((lane >> 3) & 1) * 16);

    float acc[4][2][4];
#pragma unroll
    for (int i = 0; i < 4; i++)
#pragma unroll
        for (int j = 0; j < 2; j++)
#pragma unroll
            for (int k = 0; k < 4; k++) acc[i][j][k] = 0.f;

#define ISSUE(cc, s) do { \
        int ka = ((cc) < 8) ? (cc) * 64 : 512 + ((cc) - 8) * 64; \
        int kb = ((cc) & 7) * 64; \
        _Pragma("unroll") \
        for (int i = 0; i < 4; i++) { \
            int r = sr + i * 32; \
            uint32_t da = sb + SA_OFF(s) + SW128(r * 128 + sc); \
            CP_ASYNC16(da, A + (long)(row0 + r) * KS + ka + (sc >> 1)); \
        } \
        _Pragma("unroll") \
        for (int i = 0; i < 2; i++) { \
            int r = br + i * 32; \
            uint32_t dbm = sb + SB_OFF(s) + SW128(r * 128 + sc); \
            CP_ASYNC16(dbm, B + (long)(col0 + r) * KBW + kb + (sc >> 1)); \
        } \
        CP_COMMIT(); \
    } while (0)

    ISSUE(0, 0);
    ISSUE(1, 1);

    for (int c = 0; c < NCH; c++) {
        int s = c % 3;
        CP_WAIT1();                // stage c's copies landed
        __syncthreads();           // + all warps finished reading stage (c-1)%3

        // stage (c+2)%3 == (c-1)%3 was last read in chunk c-1 -> safe to refill now;
        // copies overlap this chunk's mma work.
        if (c + 2 < NCH) ISSUE(c + 2, (c + 2) % 3);

        uint32_t sa  = sb + SA_OFF(s) + wr * (64 * 128);
        uint32_t sbm = sb + SB_OFF(s) + wc * (16 * 128);

#pragma unroll
        for (int ks = 0; ks < 4; ks++) {
            uint32_t bf[4];
            LDSM_X4(bf[0], bf[1], bf[2], bf[3], sbm + SW128(b_l + ks * 32));
#pragma unroll
            for (int mt = 0; mt < 4; mt++) {
                uint32_t af[4];
                uint32_t x = a_l + mt * 2048 + ks * 32;
                LDSM_X4(af[0], af[1], af[2], af[3], sa + SW128(x));
#pragma unroll
                for (int nt = 0; nt < 2; nt++)
                    MMA16816(acc[mt][nt], af, bf[nt * 2], bf[nt * 2 + 1]);
            }
        }
        // no trailing barrier: next iteration's top __syncthreads covers it
    }

    const int qr = lane >> 2, qc = (lane & 3) * 2;
#pragma unroll
    for (int mt = 0; mt < 4; mt++) {
#pragma unroll
        for (int nt = 0; nt < 2; nt++) {
            int r = row0 + wr * 64 + mt * 16 + qr;
            int cc = col0 + wc * 16 + nt * 8 + qc;
            *(float2*)(C + (long)r * N + cc)       = make_float2(acc[mt][nt][0], acc[mt][nt][1]);
            *(float2*)(C + (long)(r + 8) * N + cc) = make_float2(acc[mt][nt][2], acc[mt][nt][3]);
        }
    }
#undef ISSUE
}

// ---------------------------------------------------------------------------
// KNN attention v6: v5 core with unroll 8 (double per-warp gather MLP)
// + fused fp16 epilogue.
// ---------------------------------------------------------------------------
__global__ void __launch_bounds__(256) knn_attn6(
    const float* __restrict__ mem_db,
    const int*   __restrict__ knn_idx,
    const int*   __restrict__ mem_mask,
    const float* __restrict__ scale_param)
{
    __shared__ int   s_idx[8][32];
    __shared__ float s_q[8][64];
    __shared__ float s_sim[8][32];
    __shared__ float s_att[8][32];
    const unsigned FULL = 0xffffffffu;
    const int tid = threadIdx.x, lane = tid & 31, w = tid >> 5;

    const int warp = blockIdx.x * 8 + w;          // 0..32767
    const int n  = warp & (NCTX - 1);
    const int bh = warp >> 11;
    const int h  = bh & (HEADS - 1);
    const int b  = bh >> 3;

    const float* qp = g_q + ((long)(b * NCTX + n) * DIM) + h * DHEAD;
    float q0 = qp[lane], q1 = qp[lane + 32];
    float ssum = q0 * q0 + q1 * q1;
#pragma unroll
    for (int o = 16; o > 0; o >>= 1) ssum += __shfl_xor_sync(FULL, ssum, o);
    float inv = expf(scale_param[h]) / fmaxf(sqrtf(ssum), 1e-12f);
    s_q[w][lane]      = q0 * inv;
    s_q[w][lane + 32] = q1 * inv;

    long ib = (long)((b * HEADS + h) * NCTX + n) * KNN;
    s_idx[w][lane] = knn_idx[ib + lane];
    int msk = mem_mask[ib + lane];
    __syncwarp();

    const float* db = mem_db + (long)b * MDB * 128;
    const int hl = lane >> 4;
    const int sl = lane & 15;

    float4 q4 = *(const float4*)&s_q[w][sl * 4];

#pragma unroll 8
    for (int i = 0; i < 16; i++) {
        int  nb = 2 * i + hl;
        long ij = s_idx[w][nb];
        float4 k4 = *(const float4*)(db + ij * 128 + sl * 4);
        float p = fmaf(q4.x, k4.x, fmaf(q4.y, k4.y, fmaf(q4.z, k4.z, q4.w * k4.w)));
        p += __shfl_xor_sync(FULL, p, 8);
        p += __shfl_xor_sync(FULL, p, 4);
        p += __shfl_xor_sync(FULL, p, 2);
        p += __shfl_xor_sync(FULL, p, 1);
        if (sl == 0) s_sim[w][nb] = p;
    }
    __syncwarp();

    float sim = msk ? s_sim[w][lane] : -FLT_MAX;

    float m = sim;
#pragma unroll
    for (int o = 16; o > 0; o >>= 1) m = fmaxf(m, __shfl_xor_sync(FULL, m, o));
    float p = __expf(sim - m);
    float s = p;
#pragma unroll
    for (int o = 16; o > 0; o >>= 1) s += __shfl_xor_sync(FULL, s, o);
    s_att[w][lane] = p / s;
    __syncwarp();

    float4 acc = make_float4(0.f, 0.f, 0.f, 0.f);
#pragma unroll 8
    for (int i = 0; i < 16; i++) {
        int  nb = 2 * i + hl;
        long ij = s_idx[w][nb];
        float a = s_att[w][nb];
        float4 v4 = *(const float4*)(db + ij * 128 + 64 + sl * 4);
        acc.x = fmaf(a, v4.x, acc.x);
        acc.y = fmaf(a, v4.y, acc.y);
        acc.z = fmaf(a, v4.z, acc.z);
        acc.w = fmaf(a, v4.w, acc.w);
    }
    acc.x += __shfl_xor_sync(FULL, acc.x, 16);
    acc.y += __shfl_xor_sync(FULL, acc.y, 16);
    acc.z += __shfl_xor_sync(FULL, acc.z, 16);
    acc.w += __shfl_xor_sync(FULL, acc.w, 16);

    if (lane < 16) {
        float vv[4] = {acc.x, acc.y, acc.z, acc.w};
        unsigned long long hp, lp;
        split_pack4(vv, hp, lp);
        __half* dst = g_a2 + (long)(b * NCTX + n) * KS + h * DHEAD + sl * 4;
        *(unsigned long long*)(dst)       = hp;
        *(unsigned long long*)(dst + 512) = lp;
    }
}

// ---------------------------------------------------------------------------
extern "C" void kernel_launch(void* const* d_in, const int* in_sizes, int n_in,
                              void* d_out, int out_size)
{
    const float* x        = (const float*)d_in[0];
    const float* mem_db   = (const float*)d_in[1];
    const int*   knn_idx  = (const int*)d_in[2];
    const int*   mem_mask = (const int*)d_in[3];
    const float* Wq       = (const float*)d_in[4];
    // d_in[5] = Wkv : dead code in the reference, never used
    const float* Wout     = (const float*)d_in[6];
    const float* scale_p  = (const float*)d_in[7];
    float* out = (float*)d_out;

    float *qb;
    __half *a2, *b2q, *b2o;
    cudaGetSymbolAddress((void**)&qb,  g_q);
    cudaGetSymbolAddress((void**)&a2,  g_a2);
    cudaGetSymbolAddress((void**)&b2q, g_b2q);
    cudaGetSymbolAddress((void**)&b2o, g_b2o);

    cudaFuncSetAttribute(gemm_mma, cudaFuncAttributeMaxDynamicSharedMemorySize, GSMEM);

    dim3 gGemm(DIM / 64, MROWS / 128);   // (8, 32) = 256 CTAs

    // 1) split x (hi/lo), Wq, Wout (hi); then q = x @ Wq^T
    split_all<<<((MROWS + 2 * DIM) * (DIM / 4)) / 256, 256>>>(x, Wq, Wout);
    gemm_mma<<<gGemm, 256, GSMEM>>>(a2, b2q, qb, DIM);

    // 2) gather-attention; epilogue writes fp16 split directly into g_a2
    int nwarps = BATCH * HEADS * NCTX;            // 32768
    knn_attn6<<<nwarps / 8, 256>>>(mem_db, knn_idx, mem_mask, scale_p);

    // 3) out = attn_out @ Wout^T
    gemm_mma<<<gGemm, 256, GSMEM>>>(a2, b2o, out, DIM);
}

// round 15
// speedup vs baseline: 1.2048x; 1.0277x over previous
#include <cuda_runtime.h>
#include <cuda_fp16.h>
#include <math.h>
#include <float.h>
#include <stdint.h>

#define BATCH 2
#define NCTX  2048
#define DIM   512
#define HEADS 8
#define DHEAD 64
#define KNN   32
#define MDB   131072
#define MROWS (BATCH*NCTX)   // 4096
#define KS    1024           // fp16 A storage: [hi(512) | lo(512)]
#define KBW   512            // fp16 B storage: hi only
#define NCH   16             // logical K' = 1024 = 16 chunks of 64

// scratch (device globals; no allocation allowed)
__device__ float g_q[MROWS * DIM];
__device__ __half g_a2[(size_t)MROWS * KS];   // 8 MB
__device__ __half g_b2q[(size_t)DIM * KBW];   // 0.5 MB
__device__ __half g_b2o[(size_t)DIM * KBW];   // 0.5 MB

__device__ __forceinline__ uint32_t smem_u32(const void* p) {
    uint32_t a;
    asm("{ .reg .u64 t; cvta.to.shared.u64 t, %1; cvt.u32.u64 %0, t; }" : "=r"(a) : "l"(p));
    return a;
}
#define SW128(x) ((x) ^ (((x) >> 3) & 0x70))

#define LDSM_X4(r0, r1, r2, r3, addr) \
    asm volatile("ldmatrix.sync.aligned.m8n8.x4.shared.b16 {%0,%1,%2,%3}, [%4];" \
        : "=r"(r0), "=r"(r1), "=r"(r2), "=r"(r3) : "r"(addr))

#define MMA16816(c, a, b0, b1) \
    asm volatile("mma.sync.aligned.m16n8k16.row.col.f32.f16.f16.f32 " \
        "{%0,%1,%2,%3}, {%4,%5,%6,%7}, {%8,%9}, {%0,%1,%2,%3};" \
        : "+f"((c)[0]), "+f"((c)[1]), "+f"((c)[2]), "+f"((c)[3]) \
        : "r"((a)[0]), "r"((a)[1]), "r"((a)[2]), "r"((a)[3]), "r"(b0), "r"(b1))

#define CP_ASYNC16(dst, src) \
    asm volatile("cp.async.cg.shared.global [%0], [%1], 16;" :: "r"(dst), "l"(src))
#define CP_COMMIT() asm volatile("cp.async.commit_group;" ::: "memory")
#define CP_WAIT1()  asm volatile("cp.async.wait_group 1;" ::: "memory")

// ---------------------------------------------------------------------------
// split helper: 4 fp32 -> packed fp16 hi (ull) and lo (ull)
// ---------------------------------------------------------------------------
__device__ __forceinline__ void split_pack4(const float* vv,
                                            unsigned long long& hp,
                                            unsigned long long& lp)
{
    hp = 0; lp = 0;
#pragma unroll
    for (int i = 0; i < 4; i++) {
        __half h = __float2half(vv[i]);
        __half l = __float2half(vv[i] - __half2float(h));
        hp |= (unsigned long long)__half_as_ushort(h) << (16 * i);
        lp |= (unsigned long long)__half_as_ushort(l) << (16 * i);
    }
}

// A rows: [hi | lo]
__device__ __forceinline__ void split_row4_a(const float* __restrict__ src,
                                             __half* __restrict__ dst)
{
    float4 v = *(const float4*)src;
    float vv[4] = {v.x, v.y, v.z, v.w};
    unsigned long long hp, lp;
    split_pack4(vv, hp, lp);
    *(unsigned long long*)(dst)       = hp;
    *(unsigned long long*)(dst + 512) = lp;
}

// B rows: hi only
__device__ __forceinline__ void cvt_row4_b(const float* __restrict__ src,
                                           __half* __restrict__ dst)
{
    float4 v = *(const float4*)src;
    float vv[4] = {v.x, v.y, v.z, v.w};
    unsigned long long hp = 0;
#pragma unroll
    for (int i = 0; i < 4; i++)
        hp |= (unsigned long long)__half_as_ushort(__float2half(vv[i])) << (16 * i);
    *(unsigned long long*)(dst) = hp;
}

// split all inputs in one launch: x (4096 rows, hi/lo), Wq (512), Wout (512)
__global__ void split_all(const float* __restrict__ x,
                          const float* __restrict__ Wq,
                          const float* __restrict__ Wout)
{
    int idx = blockIdx.x * blockDim.x + threadIdx.x;   // over 5120*(512/4)
    int r  = idx / (DIM / 4);
    int c4 = (idx % (DIM / 4)) * 4;
    if (r < MROWS) {
        split_row4_a(x + (long)r * DIM + c4, g_a2 + (long)r * KS + c4);
    } else if (r < MROWS + DIM) {
        int rr = r - MROWS;
        cvt_row4_b(Wq + (long)rr * DIM + c4, g_b2q + (long)rr * KBW + c4);
    } else {
        int rr = r - MROWS - DIM;
        cvt_row4_b(Wout + (long)rr * DIM + c4, g_b2o + (long)rr * KBW + c4);
    }
}

// ---------------------------------------------------------------------------
// fp16 mma.sync GEMM, cp.async 3-stage pipeline, 1 barrier/chunk.
// C = A*B^T, 2-term emulated-fp32: K'=1024; chunk c<8 -> A-hi, c>=8 -> A-lo;
// B always hi block (c&7).
// CTA tile 128x64 (M x N), 8 warps (2x4), warp tile 64x16, BK=64.
// grid = (N/64, M/128) = (8, 32) = 256 CTAs, 2 CTAs/SM.
// ---------------------------------------------------------------------------
#define SA_TILE (128 * 128)       // 16 KB
#define SB_TILE (64 * 128)        // 8 KB
#define SA_OFF(s) ((s) * SA_TILE)
#define SB_OFF(s) (3 * SA_TILE + (s) * SB_TILE)
#define GSMEM  (3 * SA_TILE + 3 * SB_TILE)   // 72 KB

__global__ void __launch_bounds__(256, 2) gemm_mma(
    const __half* __restrict__ A,
    const __half* __restrict__ B,
    float* __restrict__ C, int N)
{
    extern __shared__ char smem[];
    uint32_t sb = smem_u32(smem);
    const int tid  = threadIdx.x;
    const int wid  = tid >> 5, lane = tid & 31;
    const int wr   = wid >> 2;          // 0..1 (m block of 64)
    const int wc   = wid & 3;           // 0..3 (n block of 16)
    const int row0 = blockIdx.y * 128, col0 = blockIdx.x * 64;

    const int sr = tid >> 3;            // 0..31
    const int sc = (tid & 7) * 16;      // byte col
    const int br = tid >> 3;

    const uint32_t a_l = (uint32_t)((lane & 15) * 128 + ((lane >> 4) & 1) * 16);
    const uint32_t b_l = (uint32_t)(((lane & 7) + ((lane >> 4) & 1) * 8) * 128 + ((lane >> 3) & 1) * 16);

    float acc[4][2][4];
#pragma unroll
    for (int i = 0; i < 4; i++)
#pragma unroll
        for (int j = 0; j < 2; j++)
#pragma unroll
            for (int k = 0; k < 4; k++) acc[i][j][k] = 0.f;

#define ISSUE(cc, s) do { \
        int ka = ((cc) < 8) ? (cc) * 64 : 512 + ((cc) - 8) * 64; \
        int kb = ((cc) & 7) * 64; \
        _Pragma("unroll") \
        for (int i = 0; i < 4; i++) { \
            int r = sr + i * 32; \
            uint32_t da = sb + SA_OFF(s) + SW128(r * 128 + sc); \
            CP_ASYNC16(da, A + (long)(row0 + r) * KS + ka + (sc >> 1)); \
        } \
        _Pragma("unroll") \
        for (int i = 0; i < 2; i++) { \
            int r = br + i * 32; \
            uint32_t dbm = sb + SB_OFF(s) + SW128(r * 128 + sc); \
            CP_ASYNC16(dbm, B + (long)(col0 + r) * KBW + kb + (sc >> 1)); \
        } \
        CP_COMMIT(); \
    } while (0)

    ISSUE(0, 0);
    ISSUE(1, 1);

    for (int c = 0; c < NCH; c++) {
        int s = c % 3;
        CP_WAIT1();                // stage c's copies landed
        __syncthreads();           // + all warps finished reading stage (c-1)%3

        if (c + 2 < NCH) ISSUE(c + 2, (c + 2) % 3);

        uint32_t sa  = sb + SA_OFF(s) + wr * (64 * 128);
        uint32_t sbm = sb + SB_OFF(s) + wc * (16 * 128);

#pragma unroll
        for (int ks = 0; ks < 4; ks++) {
            uint32_t bf[4];
            LDSM_X4(bf[0], bf[1], bf[2], bf[3], sbm + SW128(b_l + ks * 32));
#pragma unroll
            for (int mt = 0; mt < 4; mt++) {
                uint32_t af[4];
                uint32_t x = a_l + mt * 2048 + ks * 32;
                LDSM_X4(af[0], af[1], af[2], af[3], sa + SW128(x));
#pragma unroll
                for (int nt = 0; nt < 2; nt++)
                    MMA16816(acc[mt][nt], af, bf[nt * 2], bf[nt * 2 + 1]);
            }
        }
    }

    const int qr = lane >> 2, qc = (lane & 3) * 2;
#pragma unroll
    for (int mt = 0; mt < 4; mt++) {
#pragma unroll
        for (int nt = 0; nt < 2; nt++) {
            int r = row0 + wr * 64 + mt * 16 + qr;
            int cc = col0 + wc * 16 + nt * 8 + qc;
            *(float2*)(C + (long)r * N + cc)       = make_float2(acc[mt][nt][0], acc[mt][nt][1]);
            *(float2*)(C + (long)(r + 8) * N + cc) = make_float2(acc[mt][nt][2], acc[mt][nt][3]);
        }
    }
#undef ISSUE
}

// ---------------------------------------------------------------------------
// KNN attention v7: v6 core + mask-predicated gathers. Masked neighbors'
// k is irrelevant (sim overwritten by mask) and their softmax weight is
// exactly 0 (exp(-FLT_MAX - m)), so k/v loads are skipped -> ~50% less
// L2 gather traffic. Bit-identical semantics.
// ---------------------------------------------------------------------------
__global__ void __launch_bounds__(256) knn_attn7(
    const float* __restrict__ mem_db,
    const int*   __restrict__ knn_idx,
    const int*   __restrict__ mem_mask,
    const float* __restrict__ scale_param)
{
    __shared__ int   s_idx[8][32];
    __shared__ int   s_msk[8][32];
    __shared__ float s_q[8][64];
    __shared__ float s_sim[8][32];
    __shared__ float s_att[8][32];
    const unsigned FULL = 0xffffffffu;
    const int tid = threadIdx.x, lane = tid & 31, w = tid >> 5;

    const int warp = blockIdx.x * 8 + w;          // 0..32767
    const int n  = warp & (NCTX - 1);
    const int bh = warp >> 11;
    const int h  = bh & (HEADS - 1);
    const int b  = bh >> 3;

    const float* qp = g_q + ((long)(b * NCTX + n) * DIM) + h * DHEAD;
    float q0 = qp[lane], q1 = qp[lane + 32];
    float ssum = q0 * q0 + q1 * q1;
#pragma unroll
    for (int o = 16; o > 0; o >>= 1) ssum += __shfl_xor_sync(FULL, ssum, o);
    float inv = expf(scale_param[h]) / fmaxf(sqrtf(ssum), 1e-12f);
    s_q[w][lane]      = q0 * inv;
    s_q[w][lane + 32] = q1 * inv;

    long ib = (long)((b * HEADS + h) * NCTX + n) * KNN;
    s_idx[w][lane] = knn_idx[ib + lane];
    int msk = mem_mask[ib + lane];
    s_msk[w][lane] = msk;
    __syncwarp();

    const float* db = mem_db + (long)b * MDB * 128;
    const int hl = lane >> 4;
    const int sl = lane & 15;

    float4 q4 = *(const float4*)&s_q[w][sl * 4];

    // k phase: load only unmasked neighbors (predicated LDG; no divergence)
#pragma unroll 8
    for (int i = 0; i < 16; i++) {
        int  nb = 2 * i + hl;
        float4 k4 = make_float4(0.f, 0.f, 0.f, 0.f);
        if (s_msk[w][nb]) {
            long ij = s_idx[w][nb];
            k4 = *(const float4*)(db + ij * 128 + sl * 4);
        }
        float p = fmaf(q4.x, k4.x, fmaf(q4.y, k4.y, fmaf(q4.z, k4.z, q4.w * k4.w)));
        p += __shfl_xor_sync(FULL, p, 8);
        p += __shfl_xor_sync(FULL, p, 4);
        p += __shfl_xor_sync(FULL, p, 2);
        p += __shfl_xor_sync(FULL, p, 1);
        if (sl == 0) s_sim[w][nb] = p;
    }
    __syncwarp();

    float sim = msk ? s_sim[w][lane] : -FLT_MAX;

    float m = sim;
#pragma unroll
    for (int o = 16; o > 0; o >>= 1) m = fmaxf(m, __shfl_xor_sync(FULL, m, o));
    float p = __expf(sim - m);
    float s = p;
#pragma unroll
    for (int o = 16; o > 0; o >>= 1) s += __shfl_xor_sync(FULL, s, o);
    s_att[w][lane] = p / s;
    __syncwarp();

    // v phase: skip zero-weight neighbors (masked => weight exactly 0)
    float4 acc = make_float4(0.f, 0.f, 0.f, 0.f);
#pragma unroll 8
    for (int i = 0; i < 16; i++) {
        int  nb = 2 * i + hl;
        float a = s_att[w][nb];
        if (a != 0.f) {
            long ij = s_idx[w][nb];
            float4 v4 = *(const float4*)(db + ij * 128 + 64 + sl * 4);
            acc.x = fmaf(a, v4.x, acc.x);
            acc.y = fmaf(a, v4.y, acc.y);
            acc.z = fmaf(a, v4.z, acc.z);
            acc.w = fmaf(a, v4.w, acc.w);
        }
    }
    acc.x += __shfl_xor_sync(FULL, acc.x, 16);
    acc.y += __shfl_xor_sync(FULL, acc.y, 16);
    acc.z += __shfl_xor_sync(FULL, acc.z, 16);
    acc.w += __shfl_xor_sync(FULL, acc.w, 16);

    if (lane < 16) {
        float vv[4] = {acc.x, acc.y, acc.z, acc.w};
        unsigned long long hp, lp;
        split_pack4(vv, hp, lp);
        __half* dst = g_a2 + (long)(b * NCTX + n) * KS + h * DHEAD + sl * 4;
        *(unsigned long long*)(dst)       = hp;
        *(unsigned long long*)(dst + 512) = lp;
    }
}

// ---------------------------------------------------------------------------
extern "C" void kernel_launch(void* const* d_in, const int* in_sizes, int n_in,
                              void* d_out, int out_size)
{
    const float* x        = (const float*)d_in[0];
    const float* mem_db   = (const float*)d_in[1];
    const int*   knn_idx  = (const int*)d_in[2];
    const int*   mem_mask = (const int*)d_in[3];
    const float* Wq       = (const float*)d_in[4];
    // d_in[5] = Wkv : dead code in the reference, never used
    const float* Wout     = (const float*)d_in[6];
    const float* scale_p  = (const float*)d_in[7];
    float* out = (float*)d_out;

    float *qb;
    __half *a2, *b2q, *b2o;
    cudaGetSymbolAddress((void**)&qb,  g_q);
    cudaGetSymbolAddress((void**)&a2,  g_a2);
    cudaGetSymbolAddress((void**)&b2q, g_b2q);
    cudaGetSymbolAddress((void**)&b2o, g_b2o);

    cudaFuncSetAttribute(gemm_mma, cudaFuncAttributeMaxDynamicSharedMemorySize, GSMEM);

    dim3 gGemm(DIM / 64, MROWS / 128);   // (8, 32) = 256 CTAs

    // 1) split x (hi/lo), Wq, Wout (hi); then q = x @ Wq^T
    split_all<<<((MROWS + 2 * DIM) * (DIM / 4)) / 256, 256>>>(x, Wq, Wout);
    gemm_mma<<<gGemm, 256, GSMEM>>>(a2, b2q, qb, DIM);

    // 2) gather-attention (mask-predicated); fp16 epilogue into g_a2
    int nwarps = BATCH * HEADS * NCTX;            // 32768
    knn_attn7<<<nwarps / 8, 256>>>(mem_db, knn_idx, mem_mask, scale_p);

    // 3) out = attn_out @ Wout^T
    gemm_mma<<<gGemm, 256, GSMEM>>>(a2, b2o, out, DIM);
}

// round 16
// speedup vs baseline: 1.2437x; 1.0322x over previous
#include <cuda_runtime.h>
#include <cuda_fp16.h>
#include <math.h>
#include <float.h>
#include <stdint.h>

#define BATCH 2
#define NCTX  2048
#define DIM   512
#define HEADS 8
#define DHEAD 64
#define KNN   32
#define MDB   131072
#define MROWS (BATCH*NCTX)   // 4096
#define KS    1024           // fp16 A storage: [hi(512) | lo(512)]
#define KBW   512            // fp16 B storage: hi only
#define NCH   16             // logical K' = 1024 = 16 chunks of 64

// scratch (device globals; no allocation allowed)
__device__ float g_q[MROWS * DIM];
__device__ __half g_a2[(size_t)MROWS * KS];   // 8 MB
__device__ __half g_b2q[(size_t)DIM * KBW];   // 0.5 MB
__device__ __half g_b2o[(size_t)DIM * KBW];   // 0.5 MB

__device__ __forceinline__ uint32_t smem_u32(const void* p) {
    uint32_t a;
    asm("{ .reg .u64 t; cvta.to.shared.u64 t, %1; cvt.u32.u64 %0, t; }" : "=r"(a) : "l"(p));
    return a;
}
#define SW128(x) ((x) ^ (((x) >> 3) & 0x70))

#define LDSM_X4(r0, r1, r2, r3, addr) \
    asm volatile("ldmatrix.sync.aligned.m8n8.x4.shared.b16 {%0,%1,%2,%3}, [%4];" \
        : "=r"(r0), "=r"(r1), "=r"(r2), "=r"(r3) : "r"(addr))

#define MMA16816(c, a, b0, b1) \
    asm volatile("mma.sync.aligned.m16n8k16.row.col.f32.f16.f16.f32 " \
        "{%0,%1,%2,%3}, {%4,%5,%6,%7}, {%8,%9}, {%0,%1,%2,%3};" \
        : "+f"((c)[0]), "+f"((c)[1]), "+f"((c)[2]), "+f"((c)[3]) \
        : "r"((a)[0]), "r"((a)[1]), "r"((a)[2]), "r"((a)[3]), "r"(b0), "r"(b1))

#define CP_ASYNC16(dst, src) \
    asm volatile("cp.async.cg.shared.global [%0], [%1], 16;" :: "r"(dst), "l"(src))
#define CP_COMMIT() asm volatile("cp.async.commit_group;" ::: "memory")
#define CP_WAIT1()  asm volatile("cp.async.wait_group 1;" ::: "memory")

// ---------------------------------------------------------------------------
// split helper: 4 fp32 -> packed fp16 hi (ull) and lo (ull)
// ---------------------------------------------------------------------------
__device__ __forceinline__ void split_pack4(const float* vv,
                                            unsigned long long& hp,
                                            unsigned long long& lp)
{
    hp = 0; lp = 0;
#pragma unroll
    for (int i = 0; i < 4; i++) {
        __half h = __float2half(vv[i]);
        __half l = __float2half(vv[i] - __half2float(h));
        hp |= (unsigned long long)__half_as_ushort(h) << (16 * i);
        lp |= (unsigned long long)__half_as_ushort(l) << (16 * i);
    }
}

// A rows: [hi | lo]
__device__ __forceinline__ void split_row4_a(const float* __restrict__ src,
                                             __half* __restrict__ dst)
{
    float4 v = *(const float4*)src;
    float vv[4] = {v.x, v.y, v.z, v.w};
    unsigned long long hp, lp;
    split_pack4(vv, hp, lp);
    *(unsigned long long*)(dst)       = hp;
    *(unsigned long long*)(dst + 512) = lp;
}

// B rows: hi only
__device__ __forceinline__ void cvt_row4_b(const float* __restrict__ src,
                                           __half* __restrict__ dst)
{
    float4 v = *(const float4*)src;
    float vv[4] = {v.x, v.y, v.z, v.w};
    unsigned long long hp = 0;
#pragma unroll
    for (int i = 0; i < 4; i++)
        hp |= (unsigned long long)__half_as_ushort(__float2half(vv[i])) << (16 * i);
    *(unsigned long long*)(dst) = hp;
}

// split all inputs in one launch: x (4096 rows, hi/lo), Wq (512), Wout (512)
__global__ void split_all(const float* __restrict__ x,
                          const float* __restrict__ Wq,
                          const float* __restrict__ Wout)
{
    int idx = blockIdx.x * blockDim.x + threadIdx.x;   // over 5120*(512/4)
    int r  = idx / (DIM / 4);
    int c4 = (idx % (DIM / 4)) * 4;
    if (r < MROWS) {
        split_row4_a(x + (long)r * DIM + c4, g_a2 + (long)r * KS + c4);
    } else if (r < MROWS + DIM) {
        int rr = r - MROWS;
        cvt_row4_b(Wq + (long)rr * DIM + c4, g_b2q + (long)rr * KBW + c4);
    } else {
        int rr = r - MROWS - DIM;
        cvt_row4_b(Wout + (long)rr * DIM + c4, g_b2o + (long)rr * KBW + c4);
    }
}

// ---------------------------------------------------------------------------
// fp16 mma.sync GEMM, cp.async 3-stage pipeline, 1 barrier/chunk. (frozen)
// ---------------------------------------------------------------------------
#define SA_TILE (128 * 128)       // 16 KB
#define SB_TILE (64 * 128)        // 8 KB
#define SA_OFF(s) ((s) * SA_TILE)
#define SB_OFF(s) (3 * SA_TILE + (s) * SB_TILE)
#define GSMEM  (3 * SA_TILE + 3 * SB_TILE)   // 72 KB

__global__ void __launch_bounds__(256, 2) gemm_mma(
    const __half* __restrict__ A,
    const __half* __restrict__ B,
    float* __restrict__ C, int N)
{
    extern __shared__ char smem[];
    uint32_t sb = smem_u32(smem);
    const int tid  = threadIdx.x;
    const int wid  = tid >> 5, lane = tid & 31;
    const int wr   = wid >> 2;
    const int wc   = wid & 3;
    const int row0 = blockIdx.y * 128, col0 = blockIdx.x * 64;

    const int sr = tid >> 3;
    const int sc = (tid & 7) * 16;
    const int br = tid >> 3;

    const uint32_t a_l = (uint32_t)((lane & 15) * 128 + ((lane >> 4) & 1) * 16);
    const uint32_t b_l = (uint32_t)(((lane & 7) + ((lane >> 4) & 1) * 8) * 128 + ((lane >> 3) & 1) * 16);

    float acc[4][2][4];
#pragma unroll
    for (int i = 0; i < 4; i++)
#pragma unroll
        for (int j = 0; j < 2; j++)
#pragma unroll
            for (int k = 0; k < 4; k++) acc[i][j][k] = 0.f;

#define ISSUE(cc, s) do { \
        int ka = ((cc) < 8) ? (cc) * 64 : 512 + ((cc) - 8) * 64; \
        int kb = ((cc) & 7) * 64; \
        _Pragma("unroll") \
        for (int i = 0; i < 4; i++) { \
            int r = sr + i * 32; \
            uint32_t da = sb + SA_OFF(s) + SW128(r * 128 + sc); \
            CP_ASYNC16(da, A + (long)(row0 + r) * KS + ka + (sc >> 1)); \
        } \
        _Pragma("unroll") \
        for (int i = 0; i < 2; i++) { \
            int r = br + i * 32; \
            uint32_t dbm = sb + SB_OFF(s) + SW128(r * 128 + sc); \
            CP_ASYNC16(dbm, B + (long)(col0 + r) * KBW + kb + (sc >> 1)); \
        } \
        CP_COMMIT(); \
    } while (0)

    ISSUE(0, 0);
    ISSUE(1, 1);

    for (int c = 0; c < NCH; c++) {
        int s = c % 3;
        CP_WAIT1();
        __syncthreads();

        if (c + 2 < NCH) ISSUE(c + 2, (c + 2) % 3);

        uint32_t sa  = sb + SA_OFF(s) + wr * (64 * 128);
        uint32_t sbm = sb + SB_OFF(s) + wc * (16 * 128);

#pragma unroll
        for (int ks = 0; ks < 4; ks++) {
            uint32_t bf[4];
            LDSM_X4(bf[0], bf[1], bf[2], bf[3], sbm + SW128(b_l + ks * 32));
#pragma unroll
            for (int mt = 0; mt < 4; mt++) {
                uint32_t af[4];
                uint32_t x = a_l + mt * 2048 + ks * 32;
                LDSM_X4(af[0], af[1], af[2], af[3], sa + SW128(x));
#pragma unroll
                for (int nt = 0; nt < 2; nt++)
                    MMA16816(acc[mt][nt], af, bf[nt * 2], bf[nt * 2 + 1]);
            }
        }
    }

    const int qr = lane >> 2, qc = (lane & 3) * 2;
#pragma unroll
    for (int mt = 0; mt < 4; mt++) {
#pragma unroll
        for (int nt = 0; nt < 2; nt++) {
            int r = row0 + wr * 64 + mt * 16 + qr;
            int cc = col0 + wc * 16 + nt * 8 + qc;
            *(float2*)(C + (long)r * N + cc)       = make_float2(acc[mt][nt][0], acc[mt][nt][1]);
            *(float2*)(C + (long)(r + 8) * N + cc) = make_float2(acc[mt][nt][2], acc[mt][nt][3]);
        }
    }
#undef ISSUE
}

// ---------------------------------------------------------------------------
// KNN attention v8: single-pass online softmax. One warp per query; each
// unmasked neighbor fetched as ONE 512B contiguous LDG.128 (lanes 0-15 = k,
// lanes 16-31 = v). Ballot-compacted neighbor list + 2-deep prefetch.
// Masked neighbors never touched (exact: their softmax weight is 0).
// ---------------------------------------------------------------------------
__global__ void __launch_bounds__(256) knn_attn8(
    const float* __restrict__ mem_db,
    const int*   __restrict__ knn_idx,
    const int*   __restrict__ mem_mask,
    const float* __restrict__ scale_param)
{
    __shared__ int   s_idx[8][32];
    __shared__ float s_q[8][64];
    const unsigned FULL = 0xffffffffu;
    const int tid = threadIdx.x, lane = tid & 31, w = tid >> 5;

    const int warp = blockIdx.x * 8 + w;          // 0..32767
    const int n  = warp & (NCTX - 1);
    const int bh = warp >> 11;
    const int h  = bh & (HEADS - 1);
    const int b  = bh >> 3;

    // q load + normalize (5 shfl); scale folded in; stage to smem
    const float* qp = g_q + ((long)(b * NCTX + n) * DIM) + h * DHEAD;
    float q0 = qp[lane], q1 = qp[lane + 32];
    float nrm = q0 * q0 + q1 * q1;
#pragma unroll
    for (int o = 16; o > 0; o >>= 1) nrm += __shfl_xor_sync(FULL, nrm, o);
    float inv = expf(scale_param[h]) / fmaxf(sqrtf(nrm), 1e-12f);
    s_q[w][lane]      = q0 * inv;
    s_q[w][lane + 32] = q1 * inv;

    long ib = (long)((b * HEADS + h) * NCTX + n) * KNN;
    s_idx[w][lane] = knn_idx[ib + lane];
    int msk = mem_mask[ib + lane];
    unsigned bal = __ballot_sync(FULL, msk != 0);
    int cnt = __popc(bal);
    __syncwarp();

    const float* db = mem_db + (long)b * MDB * 128;

    // q fragment: lanes 0-15 own k dims (lane*4); lanes 16-31 compute garbage
    // partials that the broadcast discards.
    float4 q4 = *(const float4*)&s_q[w][(lane & 15) * 4];

    float mrun = -FLT_MAX, srun = 0.f;
    float4 acc = make_float4(0.f, 0.f, 0.f, 0.f);

    // prefetch first unmasked kv row (512B warp-contiguous)
    unsigned rem = bal;
    float4 d4 = make_float4(0.f, 0.f, 0.f, 0.f);
    if (cnt > 0) {
        int j0 = __ffs(rem) - 1; rem &= rem - 1;
        long ij = s_idx[w][j0];
        d4 = *(const float4*)(db + ij * 128 + lane * 4);
    }

    for (int i = 0; i < cnt; i++) {
        float4 cur = d4;
        if (i + 1 < cnt) {                   // prefetch next (MLP=2)
            int jn = __ffs(rem) - 1; rem &= rem - 1;
            long ij = s_idx[w][jn];
            d4 = *(const float4*)(db + ij * 128 + lane * 4);
        }

        // sim = q . k  (reduce over lanes 0-15, then broadcast to all)
        float p = fmaf(q4.x, cur.x, fmaf(q4.y, cur.y, fmaf(q4.z, cur.z, q4.w * cur.w)));
        p += __shfl_xor_sync(FULL, p, 8);
        p += __shfl_xor_sync(FULL, p, 4);
        p += __shfl_xor_sync(FULL, p, 2);
        p += __shfl_xor_sync(FULL, p, 1);
        float sim = __shfl_sync(FULL, p, lane & 15);

        // online softmax update (meaningful acc on lanes 16-31 = v half)
        float mnew = fmaxf(mrun, sim);
        float c   = __expf(mrun - mnew);     // exp(-inf)=0 on first iter
        float wgt = __expf(sim - mnew);
        srun = srun * c + wgt;
        acc.x = fmaf(wgt, cur.x, acc.x * c);
        acc.y = fmaf(wgt, cur.y, acc.y * c);
        acc.z = fmaf(wgt, cur.z, acc.z * c);
        acc.w = fmaf(wgt, cur.w, acc.w * c);
        mrun = mnew;
    }

    if (cnt == 0) {
        // all masked: reference softmax is uniform 1/32 over all neighbors
        for (int j = 0; j < KNN; j++) {
            long ij = s_idx[w][j];
            float4 v4 = *(const float4*)(db + ij * 128 + lane * 4);
            acc.x += v4.x; acc.y += v4.y; acc.z += v4.z; acc.w += v4.w;
        }
        srun = (float)KNN;
    }

    if (lane >= 16) {
        float is = 1.f / srun;
        float vv[4] = {acc.x * is, acc.y * is, acc.z * is, acc.w * is};
        unsigned long long hp, lp;
        split_pack4(vv, hp, lp);
        __half* dst = g_a2 + (long)(b * NCTX + n) * KS + h * DHEAD + (lane - 16) * 4;
        *(unsigned long long*)(dst)       = hp;
        *(unsigned long long*)(dst + 512) = lp;
    }
}

// ---------------------------------------------------------------------------
extern "C" void kernel_launch(void* const* d_in, const int* in_sizes, int n_in,
                              void* d_out, int out_size)
{
    const float* x        = (const float*)d_in[0];
    const float* mem_db   = (const float*)d_in[1];
    const int*   knn_idx  = (const int*)d_in[2];
    const int*   mem_mask = (const int*)d_in[3];
    const float* Wq       = (const float*)d_in[4];
    // d_in[5] = Wkv : dead code in the reference, never used
    const float* Wout     = (const float*)d_in[6];
    const float* scale_p  = (const float*)d_in[7];
    float* out = (float*)d_out;

    float *qb;
    __half *a2, *b2q, *b2o;
    cudaGetSymbolAddress((void**)&qb,  g_q);
    cudaGetSymbolAddress((void**)&a2,  g_a2);
    cudaGetSymbolAddress((void**)&b2q, g_b2q);
    cudaGetSymbolAddress((void**)&b2o, g_b2o);

    cudaFuncSetAttribute(gemm_mma, cudaFuncAttributeMaxDynamicSharedMemorySize, GSMEM);

    dim3 gGemm(DIM / 64, MROWS / 128);   // (8, 32) = 256 CTAs

    // 1) split x (hi/lo), Wq, Wout (hi); then q = x @ Wq^T
    split_all<<<((MROWS + 2 * DIM) * (DIM / 4)) / 256, 256>>>(x, Wq, Wout);
    gemm_mma<<<gGemm, 256, GSMEM>>>(a2, b2q, qb, DIM);

    // 2) single-pass online-softmax gather-attention; fp16 epilogue into g_a2
    int nwarps = BATCH * HEADS * NCTX;            // 32768
    knn_attn8<<<nwarps / 8, 256>>>(mem_db, knn_idx, mem_mask, scale_p);

    // 3) out = attn_out @ Wout^T
    gemm_mma<<<gGemm, 256, GSMEM>>>(a2, b2o, out, DIM);
}